// round 4
// baseline (speedup 1.0000x reference)
#include <cuda_runtime.h>
#include <cstdint>

#define LN_EPS 1e-5f
#define H 768
#define F 11
#define RPB 64           // rows per block in main kernel
#define MAXROWS 131072   // scratch capacity (N = 100000 in this problem)

// g_stats layout: [0..120] G[i*11+j], [121..131] ws, [132..142] Wb, [143] sum_b, [144] sum_b^2
__device__ float g_stats[145];
// per-row scratch: 32 floats (128B) per row:
//   [2k,2k+1]=feat_k duplicated (k=0..10), [22,23]=-mean dup, [24,25]=inv dup, [26..31] pad
__device__ __align__(16) float g_scratch[(size_t)MAXROWS * 32];

typedef unsigned long long ull;

__device__ __forceinline__ ull fma2(ull a, ull b, ull c) {
    ull d; asm("fma.rn.f32x2 %0, %1, %2, %3;" : "=l"(d) : "l"(a), "l"(b), "l"(c)); return d;
}
__device__ __forceinline__ ull add2(ull a, ull b) {
    ull d; asm("add.rn.f32x2 %0, %1, %2;" : "=l"(d) : "l"(a), "l"(b)); return d;
}
__device__ __forceinline__ ull mul2(ull a, ull b) {
    ull d; asm("mul.rn.f32x2 %0, %1, %2;" : "=l"(d) : "l"(a), "l"(b)); return d;
}
__device__ __forceinline__ void unpk(ull v, float& lo, float& hi) {
    asm("mov.b64 {%0, %1}, %2;" : "=f"(lo), "=f"(hi) : "l"(v));
}

// ---------------------------------------------------------------------------
// Kernel A: weight statistics (145 tiny reductions over H=768)
// ---------------------------------------------------------------------------
__global__ void stats_kernel(const float* __restrict__ W, const float* __restrict__ b) {
    __shared__ float wsum[8];
    int blk = blockIdx.x, tid = threadIdx.x;
    float local = 0.f;
    if (blk < 121) {
        int i = blk / 11, j = blk % 11;
        for (int h = tid; h < H; h += 256) local += W[i * H + h] * W[j * H + h];
    } else if (blk < 132) {
        int f = blk - 121;
        for (int h = tid; h < H; h += 256) local += W[f * H + h];
    } else if (blk < 143) {
        int f = blk - 132;
        for (int h = tid; h < H; h += 256) local += W[f * H + h] * b[h];
    } else if (blk == 143) {
        for (int h = tid; h < H; h += 256) local += b[h];
    } else {
        for (int h = tid; h < H; h += 256) local += b[h] * b[h];
    }
    #pragma unroll
    for (int o = 16; o; o >>= 1) local += __shfl_xor_sync(0xffffffffu, local, o);
    if ((tid & 31) == 0) wsum[tid >> 5] = local;
    __syncthreads();
    if (tid == 0) {
        float s = 0.f;
        #pragma unroll
        for (int w = 0; w < 8; w++) s += wsum[w];
        g_stats[blk] = s;
    }
}

// ---------------------------------------------------------------------------
// Kernel B: per-row geometric features + closed-form LayerNorm stats
// ---------------------------------------------------------------------------
__global__ void feats_kernel(const float* __restrict__ target,
                             const float* __restrict__ boxes, int N) {
    int row = blockIdx.x * blockDim.x + threadIdx.x;
    if (row >= N) return;

    float tx0 = target[0], ty0 = target[1], tx1 = target[2], ty1 = target[3];
    float4 bx = ((const float4*)boxes)[row];
    float x0 = bx.x, y0 = bx.y, x1 = bx.z, y1 = bx.w;

    float w1 = tx1 - tx0, h1 = ty1 - ty0;
    float w2 = x1 - x0,   h2 = y1 - y0;

    float t[F];
    t[0] = w1; t[1] = h1; t[2] = w2; t[3] = h2;
    t[4] = fabsf(w1 - w2); t[5] = fabsf(h1 - h2);

    float c1x = (tx0 + tx1) * 0.5f, c1y = (ty0 + ty1) * 0.5f;
    float c2x = (x0 + x1) * 0.5f,   c2y = (y0 + y1) * 0.5f;
    float dx = c2x - c1x, dy = c2y - c1y;
    t[6] = sqrtf(dx * dx + dy * dy);

    bool overlap = (tx0 < x1) && (tx1 > x0) && (ty0 < y1) && (ty1 > y0);
    float xi0 = fmaxf(tx0, x0), yi0 = fmaxf(ty0, y0);
    float xi1 = fminf(tx1, x1), yi1 = fminf(ty1, y1);
    float inter = overlap ? (xi1 - xi0) * (yi1 - yi0) : 0.f;
    float a1 = w1 * h1, a2 = w2 * h2;
    float uni = a1 + a2 - inter;
    t[7] = inter / uni; t[8] = inter / a1; t[9] = inter / a2;

    float degree = atan2f(fabsf(dy), fabsf(dx)) * 57.29577951308232f;
    float bucket;
    if      (degree >  22.5f && degree <=  67.5f) bucket = 1.f;
    else if (degree >  67.5f && degree <= 112.5f) bucket = 2.f;
    else if (degree > 112.5f && degree <= 157.5f) bucket = 3.f;
    else if (degree > 157.5f && degree <= 202.5f) bucket = 4.f;
    else if (degree > 202.5f && degree <= 247.5f) bucket = 5.f;
    else if (degree > 247.5f && degree <= 292.5f) bucket = 6.f;
    else if (degree > 292.5f && degree <= 337.5f) bucket = 7.f;
    else bucket = 8.f;
    t[10] = bucket;

    // Closed-form LayerNorm statistics:
    //   S1 = sum_h x_h  = t . ws + sum_b
    //   S2 = sum_h x_h^2 = t^T G t + 2 t . Wb + sum_b2
    const float* G  = g_stats;
    const float* ws = g_stats + 121;
    const float* Wb = g_stats + 132;
    float S1 = g_stats[143];
    float S2 = g_stats[144];
    #pragma unroll
    for (int i = 0; i < F; i++) {
        S1 += t[i] * ws[i];
        S2 += 2.f * t[i] * Wb[i];
        float gi = 0.f;
        #pragma unroll
        for (int j = 0; j < F; j++) gi += G[i * 11 + j] * t[j];
        S2 += t[i] * gi;
    }
    float mean = S1 * (1.f / (float)H);
    float var  = S2 * (1.f / (float)H) - mean * mean;
    float inv  = rsqrtf(var + LN_EPS);

    float2* sp = (float2*)(g_scratch + (size_t)row * 32);
    #pragma unroll
    for (int i = 0; i < F; i++) sp[i] = make_float2(t[i], t[i]);
    sp[11] = make_float2(-mean, -mean);
    sp[12] = make_float2(inv, inv);
    sp[13] = make_float2(0.f, 0.f);   // pad so the wide loads read defined data
}

// ---------------------------------------------------------------------------
// Kernel C: x = feats@W + b  ->  LN  ->  ReLU  (packed f32x2 math, W in regs)
// 192 threads * 4 columns = H=768; each block streams RPB rows.
// ---------------------------------------------------------------------------
__global__ void __launch_bounds__(192)
main_kernel(const float* __restrict__ W, const float* __restrict__ b,
            const float* __restrict__ gamma, const float* __restrict__ beta,
            float* __restrict__ out, int N) {
    int h0 = threadIdx.x * 4;

    ull w01[F], w23[F];
    #pragma unroll
    for (int f = 0; f < F; f++) {
        ulonglong2 q = *(const ulonglong2*)(W + f * H + h0);
        w01[f] = q.x; w23[f] = q.y;
    }
    ulonglong2 qb = *(const ulonglong2*)(b + h0);
    ulonglong2 qg = *(const ulonglong2*)(gamma + h0);
    ulonglong2 qe = *(const ulonglong2*)(beta + h0);

    int row  = blockIdx.x * RPB;
    int rend = min(row + RPB, N);
    for (; row < rend; ++row) {
        const ulonglong2* sp = (const ulonglong2*)(g_scratch + (size_t)row * 32);
        ulonglong2 q0 = sp[0], q1 = sp[1], q2 = sp[2], q3 = sp[3];
        ulonglong2 q4 = sp[4], q5 = sp[5], q6 = sp[6];
        ull ff[F] = {q0.x, q0.y, q1.x, q1.y, q2.x, q2.y, q3.x, q3.y, q4.x, q4.y, q5.x};
        ull nm2 = q5.y;   // (-mean, -mean)
        ull s2  = q6.x;   // (inv, inv)

        ull x01 = qb.x, x23 = qb.y;
        #pragma unroll
        for (int f = 0; f < F; f++) {
            x01 = fma2(ff[f], w01[f], x01);
            x23 = fma2(ff[f], w23[f], x23);
        }
        ull t01 = mul2(add2(x01, nm2), s2);
        ull t23 = mul2(add2(x23, nm2), s2);
        ull y01 = fma2(t01, qg.x, qe.x);
        ull y23 = fma2(t23, qg.y, qe.y);

        float a, bb, c, d;
        unpk(y01, a, bb);
        unpk(y23, c, d);
        float4 o;
        o.x = fmaxf(a,  0.f); o.y = fmaxf(bb, 0.f);
        o.z = fmaxf(c,  0.f); o.w = fmaxf(d,  0.f);
        *(float4*)(out + (size_t)row * H + h0) = o;
    }
}

// ---------------------------------------------------------------------------
extern "C" void kernel_launch(void* const* d_in, const int* in_sizes, int n_in,
                              void* d_out, int out_size) {
    if (n_in < 6) return;
    const float* target = (const float*)d_in[0];
    const float* boxes  = (const float*)d_in[1];
    const float* W      = (const float*)d_in[2];
    const float* b      = (const float*)d_in[3];
    const float* gamma  = (const float*)d_in[4];
    const float* beta   = (const float*)d_in[5];
    float* out = (float*)d_out;

    int N = in_sizes[1] / 4;
    if (N > MAXROWS) N = MAXROWS;

    stats_kernel<<<145, 256>>>(W, b);
    feats_kernel<<<(N + 255) / 256, 256>>>(target, boxes, N);
    main_kernel<<<(N + RPB - 1) / RPB, 192>>>(W, b, gamma, beta, out, N);
}

// round 5
// speedup vs baseline: 2.1099x; 2.1099x over previous
#include <cuda_runtime.h>
#include <cstdint>

#define LN_EPS 1e-5f
#define H 768
#define F 11
#define RPB 64           // rows per block in main kernel
#define TPB 96           // main kernel threads: 96 x 8 cols = 768
#define MAXROWS 131072

// g_stats layout: [0..120] G[i*11+j], [121..131] ws, [132..142] Wb, [143] sum_b, [144] sum_b^2
__device__ float g_stats[145];
// compact per-row scratch, 16 floats (64B):
//   [0..10]  u_f = t_f * inv
//   [11]     s   = inv
//   [12]     p   = -mean * inv
//   [13..15] pad
__device__ __align__(16) float g_scratch[(size_t)MAXROWS * 16];

typedef unsigned long long ull;

__device__ __forceinline__ ull fma2(ull a, ull b, ull c) {
    ull d; asm("fma.rn.f32x2 %0, %1, %2, %3;" : "=l"(d) : "l"(a), "l"(b), "l"(c)); return d;
}
__device__ __forceinline__ ull pk(float x) {
    ull d; asm("mov.b64 %0, {%1, %1};" : "=l"(d) : "f"(x)); return d;
}
__device__ __forceinline__ void unpk(ull v, float& lo, float& hi) {
    asm("mov.b64 {%0, %1}, %2;" : "=f"(lo), "=f"(hi) : "l"(v));
}

// ---------------------------------------------------------------------------
// Kernel A: weight statistics (145 tiny reductions over H=768)
// ---------------------------------------------------------------------------
__global__ void stats_kernel(const float* __restrict__ W, const float* __restrict__ b) {
    __shared__ float wsum[8];
    int blk = blockIdx.x, tid = threadIdx.x;
    float local = 0.f;
    if (blk < 121) {
        int i = blk / 11, j = blk % 11;
        for (int h = tid; h < H; h += 256) local += W[i * H + h] * W[j * H + h];
    } else if (blk < 132) {
        int f = blk - 121;
        for (int h = tid; h < H; h += 256) local += W[f * H + h];
    } else if (blk < 143) {
        int f = blk - 132;
        for (int h = tid; h < H; h += 256) local += W[f * H + h] * b[h];
    } else if (blk == 143) {
        for (int h = tid; h < H; h += 256) local += b[h];
    } else {
        for (int h = tid; h < H; h += 256) local += b[h] * b[h];
    }
    #pragma unroll
    for (int o = 16; o; o >>= 1) local += __shfl_xor_sync(0xffffffffu, local, o);
    if ((tid & 31) == 0) wsum[tid >> 5] = local;
    __syncthreads();
    if (tid == 0) {
        float s = 0.f;
        #pragma unroll
        for (int w = 0; w < 8; w++) s += wsum[w];
        g_stats[blk] = s;
    }
}

// ---------------------------------------------------------------------------
// Kernel B: per-row geometric features + closed-form LayerNorm stats.
// Writes inv-prescaled features so the main kernel has a pure FMA epilogue.
// ---------------------------------------------------------------------------
__global__ void feats_kernel(const float* __restrict__ target,
                             const float* __restrict__ boxes, int N) {
    int row = blockIdx.x * blockDim.x + threadIdx.x;
    if (row >= N) return;

    float tx0 = target[0], ty0 = target[1], tx1 = target[2], ty1 = target[3];
    float4 bx = ((const float4*)boxes)[row];
    float x0 = bx.x, y0 = bx.y, x1 = bx.z, y1 = bx.w;

    float w1 = tx1 - tx0, h1 = ty1 - ty0;
    float w2 = x1 - x0,   h2 = y1 - y0;

    float t[F];
    t[0] = w1; t[1] = h1; t[2] = w2; t[3] = h2;
    t[4] = fabsf(w1 - w2); t[5] = fabsf(h1 - h2);

    float c1x = (tx0 + tx1) * 0.5f, c1y = (ty0 + ty1) * 0.5f;
    float c2x = (x0 + x1) * 0.5f,   c2y = (y0 + y1) * 0.5f;
    float dx = c2x - c1x, dy = c2y - c1y;
    t[6] = sqrtf(dx * dx + dy * dy);

    bool overlap = (tx0 < x1) && (tx1 > x0) && (ty0 < y1) && (ty1 > y0);
    float xi0 = fmaxf(tx0, x0), yi0 = fmaxf(ty0, y0);
    float xi1 = fminf(tx1, x1), yi1 = fminf(ty1, y1);
    float inter = overlap ? (xi1 - xi0) * (yi1 - yi0) : 0.f;
    float a1 = w1 * h1, a2 = w2 * h2;
    float uni = a1 + a2 - inter;
    t[7] = inter / uni; t[8] = inter / a1; t[9] = inter / a2;

    float degree = atan2f(fabsf(dy), fabsf(dx)) * 57.29577951308232f;
    float bucket;
    if      (degree >  22.5f && degree <=  67.5f) bucket = 1.f;
    else if (degree >  67.5f && degree <= 112.5f) bucket = 2.f;
    else if (degree > 112.5f && degree <= 157.5f) bucket = 3.f;
    else if (degree > 157.5f && degree <= 202.5f) bucket = 4.f;
    else if (degree > 202.5f && degree <= 247.5f) bucket = 5.f;
    else if (degree > 247.5f && degree <= 292.5f) bucket = 6.f;
    else if (degree > 292.5f && degree <= 337.5f) bucket = 7.f;
    else bucket = 8.f;
    t[10] = bucket;

    // Closed-form LayerNorm statistics:
    //   S1 = t . ws + sum_b ;  S2 = t^T G t + 2 t . Wb + sum_b2
    const float* G  = g_stats;
    const float* ws = g_stats + 121;
    const float* Wb = g_stats + 132;
    float S1 = g_stats[143];
    float S2 = g_stats[144];
    #pragma unroll
    for (int i = 0; i < F; i++) {
        S1 += t[i] * ws[i];
        S2 += 2.f * t[i] * Wb[i];
        float gi = 0.f;
        #pragma unroll
        for (int j = 0; j < F; j++) gi += G[i * 11 + j] * t[j];
        S2 += t[i] * gi;
    }
    float mean = S1 * (1.f / (float)H);
    float var  = S2 * (1.f / (float)H) - mean * mean;
    float inv  = rsqrtf(var + LN_EPS);

    float4* sp = (float4*)(g_scratch + (size_t)row * 16);
    sp[0] = make_float4(t[0] * inv, t[1] * inv, t[2]  * inv, t[3] * inv);
    sp[1] = make_float4(t[4] * inv, t[5] * inv, t[6]  * inv, t[7] * inv);
    sp[2] = make_float4(t[8] * inv, t[9] * inv, t[10] * inv, inv);
    sp[3] = make_float4(-mean * inv, 0.f, 0.f, 0.f);
}

// ---------------------------------------------------------------------------
// Kernel C: acc = sum_f u_f*W_f + s*b + p ; y = relu(acc*gamma + beta)
// 96 threads x 8 columns; W slice resident in registers; one-row prefetch;
// streaming 128-bit stores.
// ---------------------------------------------------------------------------
__global__ void __launch_bounds__(TPB)
main_kernel(const float* __restrict__ W, const float* __restrict__ b,
            const float* __restrict__ gamma, const float* __restrict__ beta,
            float* __restrict__ out, int N) {
    int h0 = threadIdx.x * 8;

    ull w[F][4];
    #pragma unroll
    for (int f = 0; f < F; f++) {
        ulonglong2 a = *(const ulonglong2*)(W + f * H + h0);
        ulonglong2 c = *(const ulonglong2*)(W + f * H + h0 + 4);
        w[f][0] = a.x; w[f][1] = a.y; w[f][2] = c.x; w[f][3] = c.y;
    }
    ull bp[4], gp[4], ep[4];
    {
        ulonglong2 a = *(const ulonglong2*)(b + h0);
        ulonglong2 c = *(const ulonglong2*)(b + h0 + 4);
        bp[0] = a.x; bp[1] = a.y; bp[2] = c.x; bp[3] = c.y;
        a = *(const ulonglong2*)(gamma + h0);
        c = *(const ulonglong2*)(gamma + h0 + 4);
        gp[0] = a.x; gp[1] = a.y; gp[2] = c.x; gp[3] = c.y;
        a = *(const ulonglong2*)(beta + h0);
        c = *(const ulonglong2*)(beta + h0 + 4);
        ep[0] = a.x; ep[1] = a.y; ep[2] = c.x; ep[3] = c.y;
    }

    int row  = blockIdx.x * RPB;
    int rend = min(row + RPB, N);
    if (row >= rend) return;

    const float4* sp = (const float4*)g_scratch;
    float4 c0 = __ldg(&sp[(size_t)row * 4 + 0]);
    float4 c1 = __ldg(&sp[(size_t)row * 4 + 1]);
    float4 c2 = __ldg(&sp[(size_t)row * 4 + 2]);
    float4 c3 = __ldg(&sp[(size_t)row * 4 + 3]);

    for (; row < rend; ++row) {
        // prefetch next row's stats while computing this one
        int nr = (row + 1 < rend) ? row + 1 : row;
        float4 n0 = __ldg(&sp[(size_t)nr * 4 + 0]);
        float4 n1 = __ldg(&sp[(size_t)nr * 4 + 1]);
        float4 n2 = __ldg(&sp[(size_t)nr * 4 + 2]);
        float4 n3 = __ldg(&sp[(size_t)nr * 4 + 3]);

        ull u[F];
        u[0] = pk(c0.x); u[1] = pk(c0.y); u[2]  = pk(c0.z); u[3] = pk(c0.w);
        u[4] = pk(c1.x); u[5] = pk(c1.y); u[6]  = pk(c1.z); u[7] = pk(c1.w);
        u[8] = pk(c2.x); u[9] = pk(c2.y); u[10] = pk(c2.z);
        ull s2 = pk(c2.w);      // (inv, inv)
        ull p2 = pk(c3.x);      // (-mean*inv, -mean*inv)

        ull acc[4];
        #pragma unroll
        for (int k = 0; k < 4; k++) acc[k] = fma2(s2, bp[k], p2);
        #pragma unroll
        for (int f = 0; f < F; f++) {
            #pragma unroll
            for (int k = 0; k < 4; k++) acc[k] = fma2(u[f], w[f][k], acc[k]);
        }
        #pragma unroll
        for (int k = 0; k < 4; k++) acc[k] = fma2(acc[k], gp[k], ep[k]);

        float v0, v1, v2, v3, v4, v5, v6, v7;
        unpk(acc[0], v0, v1); unpk(acc[1], v2, v3);
        unpk(acc[2], v4, v5); unpk(acc[3], v6, v7);
        float4 o0, o1;
        o0.x = fmaxf(v0, 0.f); o0.y = fmaxf(v1, 0.f);
        o0.z = fmaxf(v2, 0.f); o0.w = fmaxf(v3, 0.f);
        o1.x = fmaxf(v4, 0.f); o1.y = fmaxf(v5, 0.f);
        o1.z = fmaxf(v6, 0.f); o1.w = fmaxf(v7, 0.f);

        float* op = out + (size_t)row * H + h0;
        __stcs((float4*)op,       o0);
        __stcs((float4*)(op + 4), o1);

        c0 = n0; c1 = n1; c2 = n2; c3 = n3;
    }
}

// ---------------------------------------------------------------------------
extern "C" void kernel_launch(void* const* d_in, const int* in_sizes, int n_in,
                              void* d_out, int out_size) {
    if (n_in < 6) return;
    const float* target = (const float*)d_in[0];
    const float* boxes  = (const float*)d_in[1];
    const float* W      = (const float*)d_in[2];
    const float* b      = (const float*)d_in[3];
    const float* gamma  = (const float*)d_in[4];
    const float* beta   = (const float*)d_in[5];
    float* out = (float*)d_out;

    int N = in_sizes[1] / 4;
    if (N > MAXROWS) N = MAXROWS;

    stats_kernel<<<145, 256>>>(W, b);
    feats_kernel<<<(N + 255) / 256, 256>>>(target, boxes, N);
    main_kernel<<<(N + RPB - 1) / RPB, TPB>>>(W, b, gamma, beta, out, N);
}

// round 6
// speedup vs baseline: 2.8464x; 1.3491x over previous
#include <cuda_runtime.h>
#include <cstdint>

#define LN_EPS 1e-5f
#define H 768
#define F 11
#define RPB 64            // rows per block
#define TPB 96            // 96 threads x 8 cols = 768
#define CHUNK 4           // rows per bulk-store chunk
#define NCHUNK (RPB / CHUNK)
#define ROWBYTES (H * 4)  // 3072

// [0..120] G[i*11+j], [121..131] ws, [132..142] Wb, [143] sum_b, [144] sum_b2
__device__ float g_stats[145];

typedef unsigned long long ull;

__device__ __forceinline__ ull fma2(ull a, ull b, ull c) {
    ull d; asm("fma.rn.f32x2 %0, %1, %2, %3;" : "=l"(d) : "l"(a), "l"(b), "l"(c)); return d;
}
__device__ __forceinline__ ull pk(float x) {
    ull d; asm("mov.b64 %0, {%1, %1};" : "=l"(d) : "f"(x)); return d;
}
__device__ __forceinline__ void unpk(ull v, float& lo, float& hi) {
    asm("mov.b64 {%0, %1}, %2;" : "=f"(lo), "=f"(hi) : "l"(v));
}
__device__ __forceinline__ uint32_t smem_u32(const void* p) {
    uint32_t a;
    asm("{ .reg .u64 t; cvta.to.shared.u64 t, %1; cvt.u32.u64 %0, t; }" : "=r"(a) : "l"(p));
    return a;
}

// ---------------------------------------------------------------------------
// Kernel A: weight statistics (145 tiny reductions over H=768)
// ---------------------------------------------------------------------------
__global__ void stats_kernel(const float* __restrict__ W, const float* __restrict__ b) {
    __shared__ float wsum[8];
    int blk = blockIdx.x, tid = threadIdx.x;
    float local = 0.f;
    if (blk < 121) {
        int i = blk / 11, j = blk % 11;
        for (int h = tid; h < H; h += 256) local += W[i * H + h] * W[j * H + h];
    } else if (blk < 132) {
        int f = blk - 121;
        for (int h = tid; h < H; h += 256) local += W[f * H + h];
    } else if (blk < 143) {
        int f = blk - 132;
        for (int h = tid; h < H; h += 256) local += W[f * H + h] * b[h];
    } else if (blk == 143) {
        for (int h = tid; h < H; h += 256) local += b[h];
    } else {
        for (int h = tid; h < H; h += 256) local += b[h] * b[h];
    }
    #pragma unroll
    for (int o = 16; o; o >>= 1) local += __shfl_xor_sync(0xffffffffu, local, o);
    if ((tid & 31) == 0) wsum[tid >> 5] = local;
    __syncthreads();
    if (tid == 0) {
        float s = 0.f;
        #pragma unroll
        for (int w = 0; w < 8; w++) s += wsum[w];
        g_stats[blk] = s;
    }
}

// ---------------------------------------------------------------------------
// Kernel B (fused): per-block feats -> smem, packed-FFMA2 GEMV+LN+ReLU into
// a double-buffered smem tile, TMA bulk stores to global.
// ---------------------------------------------------------------------------
__global__ void __launch_bounds__(TPB)
fused_kernel(const float* __restrict__ target, const float* __restrict__ boxes,
             const float* __restrict__ W, const float* __restrict__ b,
             const float* __restrict__ gamma, const float* __restrict__ beta,
             float* __restrict__ out, int N) {
    __shared__ __align__(128) float obuf[2][CHUNK * H];   // 2 x 12KB
    __shared__ __align__(16)  float fst[RPB][16];         // per-row u[11], inv, -mean*inv
    __shared__ float st[148];

    int tid = threadIdx.x;
    int h0 = tid * 8;

    // stage weight stats to smem
    for (int i = tid; i < 145; i += TPB) st[i] = g_stats[i];

    // resident W / b / gamma / beta slices (packed pairs)
    ull w[F][4];
    #pragma unroll
    for (int f = 0; f < F; f++) {
        ulonglong2 a = *(const ulonglong2*)(W + f * H + h0);
        ulonglong2 c = *(const ulonglong2*)(W + f * H + h0 + 4);
        w[f][0] = a.x; w[f][1] = a.y; w[f][2] = c.x; w[f][3] = c.y;
    }
    ull bp[4], gp[4], ep[4];
    {
        ulonglong2 a = *(const ulonglong2*)(b + h0);
        ulonglong2 c = *(const ulonglong2*)(b + h0 + 4);
        bp[0] = a.x; bp[1] = a.y; bp[2] = c.x; bp[3] = c.y;
        a = *(const ulonglong2*)(gamma + h0);
        c = *(const ulonglong2*)(gamma + h0 + 4);
        gp[0] = a.x; gp[1] = a.y; gp[2] = c.x; gp[3] = c.y;
        a = *(const ulonglong2*)(beta + h0);
        c = *(const ulonglong2*)(beta + h0 + 4);
        ep[0] = a.x; ep[1] = a.y; ep[2] = c.x; ep[3] = c.y;
    }

    int r0blk = blockIdx.x * RPB;
    __syncthreads();   // st[] ready

    // ---- feats phase: one row per thread (tid < 64) ----
    if (tid < RPB) {
        int row = r0blk + tid;
        if (row < N) {
            float tx0 = target[0], ty0 = target[1], tx1 = target[2], ty1 = target[3];
            float4 bx = ((const float4*)boxes)[row];
            float x0 = bx.x, y0 = bx.y, x1 = bx.z, y1 = bx.w;

            float w1 = tx1 - tx0, h1 = ty1 - ty0;
            float w2 = x1 - x0,   h2 = y1 - y0;

            float t[F];
            t[0] = w1; t[1] = h1; t[2] = w2; t[3] = h2;
            t[4] = fabsf(w1 - w2); t[5] = fabsf(h1 - h2);

            float c1x = (tx0 + tx1) * 0.5f, c1y = (ty0 + ty1) * 0.5f;
            float c2x = (x0 + x1) * 0.5f,   c2y = (y0 + y1) * 0.5f;
            float dx = c2x - c1x, dy = c2y - c1y;
            t[6] = sqrtf(dx * dx + dy * dy);

            bool overlap = (tx0 < x1) && (tx1 > x0) && (ty0 < y1) && (ty1 > y0);
            float xi0 = fmaxf(tx0, x0), yi0 = fmaxf(ty0, y0);
            float xi1 = fminf(tx1, x1), yi1 = fminf(ty1, y1);
            float inter = overlap ? (xi1 - xi0) * (yi1 - yi0) : 0.f;
            float a1 = w1 * h1, a2 = w2 * h2;
            float uni = a1 + a2 - inter;
            t[7] = inter / uni; t[8] = inter / a1; t[9] = inter / a2;

            float degree = atan2f(fabsf(dy), fabsf(dx)) * 57.29577951308232f;
            float bucket;
            if      (degree >  22.5f && degree <=  67.5f) bucket = 1.f;
            else if (degree >  67.5f && degree <= 112.5f) bucket = 2.f;
            else if (degree > 112.5f && degree <= 157.5f) bucket = 3.f;
            else if (degree > 157.5f && degree <= 202.5f) bucket = 4.f;
            else if (degree > 202.5f && degree <= 247.5f) bucket = 5.f;
            else if (degree > 247.5f && degree <= 292.5f) bucket = 6.f;
            else if (degree > 292.5f && degree <= 337.5f) bucket = 7.f;
            else bucket = 8.f;
            t[10] = bucket;

            // closed-form LN stats: S1 = t.ws + sum_b ; S2 = t'Gt + 2 t.Wb + sum_b2
            const float* G  = st;
            const float* ws = st + 121;
            const float* Wb = st + 132;
            float S1 = st[143];
            float S2 = st[144];
            #pragma unroll
            for (int i = 0; i < F; i++) {
                S1 += t[i] * ws[i];
                S2 += 2.f * t[i] * Wb[i];
                float gi = 0.f;
                #pragma unroll
                for (int j = 0; j < F; j++) gi += G[i * 11 + j] * t[j];
                S2 += t[i] * gi;
            }
            float mean = S1 * (1.f / (float)H);
            float var  = S2 * (1.f / (float)H) - mean * mean;
            float inv  = rsqrtf(var + LN_EPS);

            float* fp = fst[tid];
            #pragma unroll
            for (int i = 0; i < F; i++) fp[i] = t[i] * inv;
            fp[11] = inv;
            fp[12] = -mean * inv;
            fp[13] = 0.f; fp[14] = 0.f; fp[15] = 0.f;
        }
    }
    __syncthreads();

    // ---- chunk loop: compute into smem, bulk-store to global ----
    for (int c = 0; c < NCHUNK; ++c) {
        int cr0 = r0blk + c * CHUNK;
        if (cr0 >= N) break;
        int nrows = min(CHUNK, N - cr0);
        float* buf = obuf[c & 1];

        if (c >= 2) {
            if (tid == 0)
                asm volatile("cp.async.bulk.wait_group 1;" ::: "memory");
            __syncthreads();   // buffer (c&1) free for reuse
        }

        for (int i = 0; i < nrows; ++i) {
            const float4* fq = (const float4*)fst[c * CHUNK + i];
            float4 a0 = fq[0], a1 = fq[1], a2 = fq[2], a3 = fq[3];
            ull u[F];
            u[0] = pk(a0.x); u[1] = pk(a0.y); u[2]  = pk(a0.z); u[3] = pk(a0.w);
            u[4] = pk(a1.x); u[5] = pk(a1.y); u[6]  = pk(a1.z); u[7] = pk(a1.w);
            u[8] = pk(a2.x); u[9] = pk(a2.y); u[10] = pk(a2.z);
            ull s2 = pk(a2.w);     // (inv, inv)
            ull p2 = pk(a3.x);     // (-mean*inv, ..)

            ull acc[4];
            #pragma unroll
            for (int k = 0; k < 4; k++) acc[k] = fma2(s2, bp[k], p2);
            #pragma unroll
            for (int f = 0; f < F; f++) {
                #pragma unroll
                for (int k = 0; k < 4; k++) acc[k] = fma2(u[f], w[f][k], acc[k]);
            }
            #pragma unroll
            for (int k = 0; k < 4; k++) acc[k] = fma2(acc[k], gp[k], ep[k]);

            float v0, v1, v2, v3, v4, v5, v6, v7;
            unpk(acc[0], v0, v1); unpk(acc[1], v2, v3);
            unpk(acc[2], v4, v5); unpk(acc[3], v6, v7);
            float4 o0, o1;
            o0.x = fmaxf(v0, 0.f); o0.y = fmaxf(v1, 0.f);
            o0.z = fmaxf(v2, 0.f); o0.w = fmaxf(v3, 0.f);
            o1.x = fmaxf(v4, 0.f); o1.y = fmaxf(v5, 0.f);
            o1.z = fmaxf(v6, 0.f); o1.w = fmaxf(v7, 0.f);

            float4* op = (float4*)(buf + i * H + h0);
            op[0] = o0; op[1] = o1;
        }

        asm volatile("fence.proxy.async.shared::cta;" ::: "memory");
        __syncthreads();   // tile complete and fenced

        if (tid == 0) {
            uint32_t saddr = smem_u32(buf);
            const void* gptr = (const void*)(out + (size_t)cr0 * H);
            uint32_t bytes = (uint32_t)nrows * ROWBYTES;
            asm volatile(
                "cp.async.bulk.global.shared::cta.bulk_group [%0], [%1], %2;"
                :: "l"(gptr), "r"(saddr), "r"(bytes) : "memory");
            asm volatile("cp.async.bulk.commit_group;" ::: "memory");
        }
    }

    if (tid == 0)
        asm volatile("cp.async.bulk.wait_group 0;" ::: "memory");
}

// ---------------------------------------------------------------------------
extern "C" void kernel_launch(void* const* d_in, const int* in_sizes, int n_in,
                              void* d_out, int out_size) {
    if (n_in < 6) return;
    const float* target = (const float*)d_in[0];
    const float* boxes  = (const float*)d_in[1];
    const float* W      = (const float*)d_in[2];
    const float* b      = (const float*)d_in[3];
    const float* gamma  = (const float*)d_in[4];
    const float* beta   = (const float*)d_in[5];
    float* out = (float*)d_out;

    int N = in_sizes[1] / 4;

    stats_kernel<<<145, 256>>>(W, b);
    fused_kernel<<<(N + RPB - 1) / RPB, TPB>>>(target, boxes, W, b, gamma, beta, out, N);
}